// round 2
// baseline (speedup 1.0000x reference)
#include <cuda_runtime.h>

// Problem constants
#define NE 16
#define NH 2048
#define NI 1408
#define NK 2
#define NT 8192
#define CAP (NT * NK)   // 16384 routed slots total

// ---------------- scratch (device globals; no cudaMalloc allowed) -----------
__device__ int   g_counts[NE];
__device__ int   g_fill[NE];
__device__ int   g_offsets[NE + 1];
__device__ int   g_slot_token[CAP];
__device__ float g_slot_w[CAP];
__device__ int   g_is64;
// h = silu(gate)*up for each routed slot, compact layout: [CAP, NI]  (~92 MB)
__device__ __align__(16) float g_h[(size_t)CAP * NI];

// ---------------- dtype detection for top_k_index -----------------
// JAX with x64 disabled silently downgrades int64->int32; detect at runtime.
// View buffer as int32 pairs: if 256 consecutive pairs all look like
// (value in [0,16), 0), the data is little-endian int64. Reading 512 int32s
// is in-bounds under both interpretations (int32 buffer has CAP=16384 words).
__global__ void k_detect(const int* __restrict__ idx32) {
    if (threadIdx.x == 0) {
        int is64 = 1;
        for (int i = 0; i < 256; i++) {
            int lo = idx32[2 * i];
            int hi = idx32[2 * i + 1];
            if (hi != 0 || lo < 0 || lo >= NE) { is64 = 0; break; }
        }
        g_is64 = is64;
    }
}

__device__ __forceinline__ int load_expert(const void* idx, int s) {
    if (g_is64) return (int)((const long long*)idx)[s];
    return ((const int*)idx)[s];
}

// ---------------- routing -----------------
__global__ void k_reset() {
    int i = threadIdx.x;
    if (i < NE) { g_counts[i] = 0; g_fill[i] = 0; }
}

__global__ void k_count(const void* __restrict__ idx) {
    int s = blockIdx.x * blockDim.x + threadIdx.x;
    if (s < CAP) {
        int e = load_expert(idx, s);
        if (e >= 0 && e < NE) atomicAdd(&g_counts[e], 1);
    }
}

__global__ void k_scan() {
    if (threadIdx.x == 0) {
        int acc = 0;
        for (int e = 0; e < NE; e++) { g_offsets[e] = acc; acc += g_counts[e]; }
        g_offsets[NE] = acc;
    }
}

__global__ void k_scatter(const void* __restrict__ idx,
                          const float* __restrict__ w) {
    int s = blockIdx.x * blockDim.x + threadIdx.x;
    if (s < CAP) {
        int e = load_expert(idx, s);
        if (e >= 0 && e < NE) {
            int p = g_offsets[e] + atomicAdd(&g_fill[e], 1);
            g_slot_token[p] = s / NK;
            g_slot_w[p]     = w[s];
        }
    }
}

// ---------------- GEMM 1: gathered tokens x gate_up, fused SwiGLU ----------
// C-tile: 128 (M: routed slots) x 128 (N: intermediate i in [0,NI))
// For each N column we need BOTH gate row (i) and up row (NI+i) of W_gu.
// K = NH = 2048, stepped 16 at a time through shared memory.
#define TM 128
#define TN 128
#define TKS 16

__global__ __launch_bounds__(256, 1)
void k_gemm1(const float* __restrict__ hidden,
             const float* __restrict__ Wgu /* [NE, 2*NI, NH] */) {
    const int e     = blockIdx.z;
    const int start = g_offsets[e];
    const int M     = g_offsets[e + 1] - start;
    const int m0    = blockIdx.y * TM;
    if (m0 >= M) return;
    const int n0 = blockIdx.x * TN;       // gridDim.x = NI/TN = 11 (exact)

    __shared__ float As[TKS][TM + 4];
    __shared__ float Bg[TKS][TN + 4];
    __shared__ float Bu[TKS][TN + 4];

    const int tid = threadIdx.x;
    const int ty  = tid >> 4;             // 0..15
    const int tx  = tid & 15;             // 0..15

    const float* We = Wgu + (size_t)e * (2 * NI) * NH;

    float acc_g[8][8], acc_u[8][8];
#pragma unroll
    for (int i = 0; i < 8; i++)
#pragma unroll
        for (int j = 0; j < 8; j++) { acc_g[i][j] = 0.f; acc_u[i][j] = 0.f; }

    for (int kk = 0; kk < NH; kk += TKS) {
        // A tile: TM x TKS = 2048 floats = 512 float4; 2 per thread
#pragma unroll
        for (int q = 0; q < 2; q++) {
            int id = tid + 256 * q;
            int m  = id >> 2;
            int k4 = (id & 3) * 4;
            float4 v = make_float4(0.f, 0.f, 0.f, 0.f);
            int row = m0 + m;
            if (row < M) {
                int tok = g_slot_token[start + row];
                v = *(const float4*)(hidden + (size_t)tok * NH + kk + k4);
            }
            As[k4 + 0][m] = v.x; As[k4 + 1][m] = v.y;
            As[k4 + 2][m] = v.z; As[k4 + 3][m] = v.w;
        }
        // B tiles (gate + up): each TN x TKS
#pragma unroll
        for (int q = 0; q < 2; q++) {
            int id = tid + 256 * q;
            int n  = id >> 2;
            int k4 = (id & 3) * 4;
            int col = n0 + n;             // always < NI
            float4 vg = *(const float4*)(We + (size_t)col * NH + kk + k4);
            float4 vu = *(const float4*)(We + (size_t)(col + NI) * NH + kk + k4);
            Bg[k4 + 0][n] = vg.x; Bg[k4 + 1][n] = vg.y;
            Bg[k4 + 2][n] = vg.z; Bg[k4 + 3][n] = vg.w;
            Bu[k4 + 0][n] = vu.x; Bu[k4 + 1][n] = vu.y;
            Bu[k4 + 2][n] = vu.z; Bu[k4 + 3][n] = vu.w;
        }
        __syncthreads();

#pragma unroll
        for (int k = 0; k < TKS; k++) {
            float a[8], bg[8], bu[8];
            float4 t0 = *(const float4*)&As[k][ty * 8];
            float4 t1 = *(const float4*)&As[k][ty * 8 + 4];
            a[0]=t0.x; a[1]=t0.y; a[2]=t0.z; a[3]=t0.w;
            a[4]=t1.x; a[5]=t1.y; a[6]=t1.z; a[7]=t1.w;
            float4 g0 = *(const float4*)&Bg[k][tx * 8];
            float4 g1 = *(const float4*)&Bg[k][tx * 8 + 4];
            bg[0]=g0.x; bg[1]=g0.y; bg[2]=g0.z; bg[3]=g0.w;
            bg[4]=g1.x; bg[5]=g1.y; bg[6]=g1.z; bg[7]=g1.w;
            float4 u0 = *(const float4*)&Bu[k][tx * 8];
            float4 u1 = *(const float4*)&Bu[k][tx * 8 + 4];
            bu[0]=u0.x; bu[1]=u0.y; bu[2]=u0.z; bu[3]=u0.w;
            bu[4]=u1.x; bu[5]=u1.y; bu[6]=u1.z; bu[7]=u1.w;
#pragma unroll
            for (int i = 0; i < 8; i++)
#pragma unroll
                for (int j = 0; j < 8; j++) {
                    acc_g[i][j] += a[i] * bg[j];
                    acc_u[i][j] += a[i] * bu[j];
                }
        }
        __syncthreads();
    }

    // Epilogue: h = silu(gate) * up
#pragma unroll
    for (int i = 0; i < 8; i++) {
        int row = m0 + ty * 8 + i;
        if (row >= M) continue;
        float* hrow = g_h + (size_t)(start + row) * NI + n0 + tx * 8;
#pragma unroll
        for (int j = 0; j < 8; j++) {
            float gv = acc_g[i][j];
            float s  = gv / (1.f + __expf(-gv));
            hrow[j]  = s * acc_u[i][j];
        }
    }
}

// ---------------- GEMM 2: h x down^T, weighted atomic scatter to out -------
// C-tile: 128 (M: routed slots) x 128 (N: hidden dim h in [0,NH))
// K = NI = 1408. A rows are the compact g_h rows (no gather).
__global__ __launch_bounds__(256, 1)
void k_gemm2(const float* __restrict__ down /* [NE, NH, NI] */,
             float* __restrict__ out) {
    const int e     = blockIdx.z;
    const int start = g_offsets[e];
    const int M     = g_offsets[e + 1] - start;
    const int m0    = blockIdx.y * TM;
    if (m0 >= M) return;
    const int n0 = blockIdx.x * TN;       // gridDim.x = NH/TN = 16

    __shared__ float As[TKS][TM + 4];
    __shared__ float Bs[TKS][TN + 4];

    const int tid = threadIdx.x;
    const int ty  = tid >> 4;
    const int tx  = tid & 15;

    const float* De = down + (size_t)e * NH * NI;

    float acc[8][8];
#pragma unroll
    for (int i = 0; i < 8; i++)
#pragma unroll
        for (int j = 0; j < 8; j++) acc[i][j] = 0.f;

    for (int kk = 0; kk < NI; kk += TKS) {
#pragma unroll
        for (int q = 0; q < 2; q++) {
            int id = tid + 256 * q;
            int m  = id >> 2;
            int k4 = (id & 3) * 4;
            float4 v = make_float4(0.f, 0.f, 0.f, 0.f);
            int row = m0 + m;
            if (row < M)
                v = *(const float4*)(g_h + (size_t)(start + row) * NI + kk + k4);
            As[k4 + 0][m] = v.x; As[k4 + 1][m] = v.y;
            As[k4 + 2][m] = v.z; As[k4 + 3][m] = v.w;
        }
#pragma unroll
        for (int q = 0; q < 2; q++) {
            int id = tid + 256 * q;
            int n  = id >> 2;
            int k4 = (id & 3) * 4;
            int col = n0 + n;             // < NH always
            float4 v = *(const float4*)(De + (size_t)col * NI + kk + k4);
            Bs[k4 + 0][n] = v.x; Bs[k4 + 1][n] = v.y;
            Bs[k4 + 2][n] = v.z; Bs[k4 + 3][n] = v.w;
        }
        __syncthreads();

#pragma unroll
        for (int k = 0; k < TKS; k++) {
            float a[8], b[8];
            float4 t0 = *(const float4*)&As[k][ty * 8];
            float4 t1 = *(const float4*)&As[k][ty * 8 + 4];
            a[0]=t0.x; a[1]=t0.y; a[2]=t0.z; a[3]=t0.w;
            a[4]=t1.x; a[5]=t1.y; a[6]=t1.z; a[7]=t1.w;
            float4 b0 = *(const float4*)&Bs[k][tx * 8];
            float4 b1 = *(const float4*)&Bs[k][tx * 8 + 4];
            b[0]=b0.x; b[1]=b0.y; b[2]=b0.z; b[3]=b0.w;
            b[4]=b1.x; b[5]=b1.y; b[6]=b1.z; b[7]=b1.w;
#pragma unroll
            for (int i = 0; i < 8; i++)
#pragma unroll
                for (int j = 0; j < 8; j++)
                    acc[i][j] += a[i] * b[j];
        }
        __syncthreads();
    }

    // Epilogue: out[tok, n] += w * acc  (a token can appear in 2 slots -> atomics)
#pragma unroll
    for (int i = 0; i < 8; i++) {
        int row = m0 + ty * 8 + i;
        if (row >= M) continue;
        int p    = start + row;
        int tok  = g_slot_token[p];
        float w  = g_slot_w[p];
        float* orow = out + (size_t)tok * NH + n0 + tx * 8;
#pragma unroll
        for (int j = 0; j < 8; j++)
            atomicAdd(&orow[j], acc[i][j] * w);
    }
}

// ---------------- launch -----------------
extern "C" void kernel_launch(void* const* d_in, const int* in_sizes, int n_in,
                              void* d_out, int out_size) {
    const float* hidden = (const float*)d_in[0];   // [T, H]
    const void*  idx    = d_in[1];                 // [T, K] int32 or int64
    const float* wts    = (const float*)d_in[2];   // [T, K]
    const float* wgu    = (const float*)d_in[3];   // [E, 2I, H]
    const float* wdn    = (const float*)d_in[4];   // [E, H, I]

    (void)in_sizes; (void)n_in;

    k_detect<<<1, 32>>>((const int*)idx);
    k_reset<<<1, 32>>>();
    k_count<<<(CAP + 255) / 256, 256>>>(idx);
    k_scan<<<1, 32>>>();
    k_scatter<<<(CAP + 255) / 256, 256>>>(idx, wts);

    cudaMemsetAsync(d_out, 0, (size_t)out_size * sizeof(float), 0);

    // GEMM1: grid x over NI tiles (11), y over worst-case M tiles, z experts
    dim3 g1(NI / TN, (CAP + TM - 1) / TM, NE);
    k_gemm1<<<g1, 256>>>(hidden, wgu);

    // GEMM2: grid x over NH tiles (16)
    dim3 g2(NH / TN, (CAP + TM - 1) / TM, NE);
    k_gemm2<<<g2, 256>>>(wdn, (float*)d_out);
}

// round 4
// speedup vs baseline: 2.3480x; 2.3480x over previous
#include <cuda_runtime.h>
#include <cuda_bf16.h>
#include <cstdint>

// Problem constants
#define NE 16
#define NH 2048
#define NI 1408
#define NK 2
#define NT 8192
#define CAP (NT * NK)   // 16384 routed slots

// ---------------- scratch (device globals; no cudaMalloc allowed) ----------
__device__ int   g_counts[NE];
__device__ int   g_fill[NE];
__device__ int   g_offsets[NE + 1];
__device__ int   g_slot_token[CAP];
__device__ float g_slot_w[CAP];
__device__ int   g_is64;

// bf16 split operands (hi + lo), K-major row layouts matching sources
__device__ __align__(16) __nv_bfloat16 g_hid_hi[(size_t)NT * NH];
__device__ __align__(16) __nv_bfloat16 g_hid_lo[(size_t)NT * NH];
__device__ __align__(16) __nv_bfloat16 g_wgu_hi[(size_t)NE * 2 * NI * NH];
__device__ __align__(16) __nv_bfloat16 g_wgu_lo[(size_t)NE * 2 * NI * NH];
__device__ __align__(16) __nv_bfloat16 g_wdn_hi[(size_t)NE * NH * NI];
__device__ __align__(16) __nv_bfloat16 g_wdn_lo[(size_t)NE * NH * NI];
__device__ __align__(16) __nv_bfloat16 g_h_hi[(size_t)CAP * NI];
__device__ __align__(16) __nv_bfloat16 g_h_lo[(size_t)CAP * NI];

// ---------------- PTX helpers (baseline ISA only: sm_80+ features) ---------
__device__ __forceinline__ uint32_t smem_u32(const void* p) {
    uint32_t a;
    asm("{ .reg .u64 t; cvta.to.shared.u64 t, %1; cvt.u32.u64 %0, t; }" : "=r"(a) : "l"(p));
    return a;
}
#define CP_ASYNC16(dst, src) \
    asm volatile("cp.async.cg.shared.global [%0], [%1], 16;" :: "r"(dst), "l"(src))
#define CP_COMMIT() asm volatile("cp.async.commit_group;" ::: "memory")
#define CP_WAIT(N)  asm volatile("cp.async.wait_group %0;" :: "n"(N) : "memory")

#define LDSM4(r, addr) \
    asm volatile("ldmatrix.sync.aligned.m8n8.x4.shared.b16 {%0,%1,%2,%3}, [%4];" \
        : "=r"((r)[0]), "=r"((r)[1]), "=r"((r)[2]), "=r"((r)[3]) : "r"(addr))

#define MMA16816(c, a, b0_, b1_) \
    asm volatile("mma.sync.aligned.m16n8k16.row.col.f32.bf16.bf16.f32 " \
        "{%0,%1,%2,%3}, {%4,%5,%6,%7}, {%8,%9}, {%0,%1,%2,%3};" \
        : "+f"((c)[0]), "+f"((c)[1]), "+f"((c)[2]), "+f"((c)[3]) \
        : "r"((a)[0]), "r"((a)[1]), "r"((a)[2]), "r"((a)[3]), "r"(b0_), "r"(b1_))

// ---------------- dtype detection for top_k_index -----------------
__global__ void k_detect(const int* __restrict__ idx32) {
    if (threadIdx.x == 0) {
        int is64 = 1;
        for (int i = 0; i < 256; i++) {
            int lo = idx32[2 * i], hi = idx32[2 * i + 1];
            if (hi != 0 || lo < 0 || lo >= NE) { is64 = 0; break; }
        }
        g_is64 = is64;
    }
}
__device__ __forceinline__ int load_expert(const void* idx, int s) {
    if (g_is64) return (int)((const long long*)idx)[s];
    return ((const int*)idx)[s];
}

// ---------------- routing -----------------
__global__ void k_reset() {
    int i = threadIdx.x;
    if (i < NE) { g_counts[i] = 0; g_fill[i] = 0; }
}
__global__ void k_count(const void* __restrict__ idx) {
    int s = blockIdx.x * blockDim.x + threadIdx.x;
    if (s < CAP) {
        int e = load_expert(idx, s);
        if (e >= 0 && e < NE) atomicAdd(&g_counts[e], 1);
    }
}
__global__ void k_scan() {
    if (threadIdx.x == 0) {
        int acc = 0;
        for (int e = 0; e < NE; e++) { g_offsets[e] = acc; acc += g_counts[e]; }
        g_offsets[NE] = acc;
    }
}
__global__ void k_scatter(const void* __restrict__ idx, const float* __restrict__ w) {
    int s = blockIdx.x * blockDim.x + threadIdx.x;
    if (s < CAP) {
        int e = load_expert(idx, s);
        if (e >= 0 && e < NE) {
            int p = g_offsets[e] + atomicAdd(&g_fill[e], 1);
            g_slot_token[p] = s / NK;
            g_slot_w[p]     = w[s];
        }
    }
}

// ---------------- fp32 -> bf16 hi/lo split conversions ----------------
__device__ __forceinline__ void cvt_body(const float4* __restrict__ s,
                                         __nv_bfloat162* __restrict__ hi,
                                         __nv_bfloat162* __restrict__ lo, size_t n4) {
    size_t i = (size_t)blockIdx.x * blockDim.x + threadIdx.x;
    size_t stride = (size_t)gridDim.x * blockDim.x;
    for (; i < n4; i += stride) {
        float4 v = s[i];
        __nv_bfloat16 hx = __float2bfloat16(v.x), hy = __float2bfloat16(v.y);
        __nv_bfloat16 hz = __float2bfloat16(v.z), hw = __float2bfloat16(v.w);
        __nv_bfloat162 h0; h0.x = hx; h0.y = hy;
        __nv_bfloat162 h1; h1.x = hz; h1.y = hw;
        hi[2 * i]     = h0;
        hi[2 * i + 1] = h1;
        __nv_bfloat162 l0, l1;
        l0.x = __float2bfloat16(v.x - __bfloat162float(hx));
        l0.y = __float2bfloat16(v.y - __bfloat162float(hy));
        l1.x = __float2bfloat16(v.z - __bfloat162float(hz));
        l1.y = __float2bfloat16(v.w - __bfloat162float(hw));
        lo[2 * i]     = l0;
        lo[2 * i + 1] = l1;
    }
}
__global__ void k_cvt_hid(const float4* __restrict__ s) {
    cvt_body(s, (__nv_bfloat162*)g_hid_hi, (__nv_bfloat162*)g_hid_lo, (size_t)NT * NH / 4);
}
__global__ void k_cvt_wgu(const float4* __restrict__ s) {
    cvt_body(s, (__nv_bfloat162*)g_wgu_hi, (__nv_bfloat162*)g_wgu_lo, (size_t)NE * 2 * NI * NH / 4);
}
__global__ void k_cvt_wdn(const float4* __restrict__ s) {
    cvt_body(s, (__nv_bfloat162*)g_wdn_hi, (__nv_bfloat162*)g_wdn_lo, (size_t)NE * NH * NI / 4);
}

// ---------------- HMMA GEMMs ----------------
// SMEM per stage: 4 tiles (Ah, Al, Bh, Bl), each 128 rows x 64 bf16 cols with
// stride 72 elems (144 B; row-start banks 0,4,...,28 -> conflict-free ldmatrix).
// Only cols 0..63 are loaded (pad cols never read).
#define ROW_B   144
#define TILE_BB (128 * ROW_B)         // 18432 B
#define STAGE_B (4 * TILE_BB)         // 73728 B
#define SMEM_TOT (2 * STAGE_B)        // 147456 B

// Warp layout: 8 warps, warp w owns rows [w*16, w*16+16), all 128 N cols.
// Per k16 step: A frags (hi+lo), 8 n16 B groups (hi+lo), 48 MMAs.

// ---- GEMM1: C[128 slots, 64 gate | 64 up], K = NH, 32 chunks of 64 ----
__global__ __launch_bounds__(256, 1) void k_gemm1() {
    extern __shared__ char smem[];
    const int e     = blockIdx.z;
    const int start = g_offsets[e];
    const int M     = g_offsets[e + 1] - start;
    const int m0    = blockIdx.y * 128;
    if (m0 >= M) return;
    const int i0 = blockIdx.x * 64;     // gridDim.x = NI/64 = 22

    const int tid  = threadIdx.x;
    const int wid  = tid >> 5;
    const int lane = tid & 31;
    uint32_t sb = smem_u32(smem);

    // per-thread cp.async rows: vec id v = tid + 256*i -> row v>>3, col8 = v&7
    const int vrow = tid >> 3;
    const int col8 = tid & 7;
    size_t arow[4], brow[4];
#pragma unroll
    for (int i = 0; i < 4; i++) {
        int row = vrow + 32 * i;
        int ar  = m0 + row; if (ar >= M) ar = M - 1;
        arow[i] = (size_t)g_slot_token[start + ar] * NH;
        int wr  = (row < 64) ? (i0 + row) : (NI + i0 + row - 64);
        brow[i] = (size_t)e * (2 * NI) * NH + (size_t)wr * NH;
    }

    auto issue = [&](int s, int kk) {
        uint32_t base = sb + s * STAGE_B;
#pragma unroll
        for (int i = 0; i < 4; i++) {
            int row = vrow + 32 * i;
            uint32_t d = base + row * ROW_B + col8 * 16;
            CP_ASYNC16(d + 0 * TILE_BB, g_hid_hi + arow[i] + kk + col8 * 8);
            CP_ASYNC16(d + 1 * TILE_BB, g_hid_lo + arow[i] + kk + col8 * 8);
            CP_ASYNC16(d + 2 * TILE_BB, g_wgu_hi + brow[i] + kk + col8 * 8);
            CP_ASYNC16(d + 3 * TILE_BB, g_wgu_lo + brow[i] + kk + col8 * 8);
        }
    };

    float acc[16][4];
#pragma unroll
    for (int q = 0; q < 16; q++)
#pragma unroll
        for (int i = 0; i < 4; i++) acc[q][i] = 0.f;

    const uint32_t a_off = (uint32_t)((wid * 16 + (lane & 15)) * ROW_B + (lane >> 4) * 16);
    const uint32_t b_off = (uint32_t)(((lane & 7) + ((lane >> 4) & 1) * 8) * ROW_B +
                                      ((lane >> 3) & 1) * 16);

    issue(0, 0);
    CP_COMMIT();

    for (int c = 0; c < NH / 64; c++) {
        if (c + 1 < NH / 64) { issue((c + 1) & 1, (c + 1) * 64); CP_COMMIT(); CP_WAIT(1); }
        else                 { CP_WAIT(0); }
        __syncthreads();
        uint32_t base = sb + (c & 1) * STAGE_B;
#pragma unroll
        for (int kk = 0; kk < 4; kk++) {
            uint32_t ah[4], al[4];
            LDSM4(ah, base + 0 * TILE_BB + a_off + kk * 32);
            LDSM4(al, base + 1 * TILE_BB + a_off + kk * 32);
#pragma unroll
            for (int nt = 0; nt < 8; nt++) {
                uint32_t bh[4], bl[4];
                uint32_t bo = b_off + nt * (16 * ROW_B) + kk * 32;
                LDSM4(bh, base + 2 * TILE_BB + bo);
                LDSM4(bl, base + 3 * TILE_BB + bo);
                MMA16816(acc[2 * nt],     ah, bh[0], bh[1]);
                MMA16816(acc[2 * nt],     ah, bl[0], bl[1]);
                MMA16816(acc[2 * nt],     al, bh[0], bh[1]);
                MMA16816(acc[2 * nt + 1], ah, bh[2], bh[3]);
                MMA16816(acc[2 * nt + 1], ah, bl[2], bl[3]);
                MMA16816(acc[2 * nt + 1], al, bh[2], bh[3]);
            }
        }
        __syncthreads();
    }

    // epilogue: cols 0..63 = gate(i0+j), 64..127 = up(i0+j); h = silu(g)*u
    const int r0 = m0 + wid * 16 + (lane >> 2);
    const int r1 = r0 + 8;
    const int cb = (lane & 3) * 2;
#pragma unroll
    for (int q = 0; q < 8; q++) {
        int col = i0 + q * 8 + cb;
#pragma unroll
        for (int half = 0; half < 2; half++) {   // half 0: rows r0 (regs 0,1); 1: r1 (2,3)
            int row = half ? r1 : r0;
            if (row >= M) continue;
            float g0 = acc[q][2 * half + 0],     g1 = acc[q][2 * half + 1];
            float u0 = acc[q + 8][2 * half + 0], u1 = acc[q + 8][2 * half + 1];
            float h0 = u0 * g0 / (1.f + __expf(-g0));
            float h1 = u1 * g1 / (1.f + __expf(-g1));
            __nv_bfloat16 hh0 = __float2bfloat16(h0), hh1 = __float2bfloat16(h1);
            __nv_bfloat162 ph; ph.x = hh0; ph.y = hh1;
            __nv_bfloat162 pl;
            pl.x = __float2bfloat16(h0 - __bfloat162float(hh0));
            pl.y = __float2bfloat16(h1 - __bfloat162float(hh1));
            size_t o = (size_t)(start + row) * NI + col;
            *(__nv_bfloat162*)(g_h_hi + o) = ph;
            *(__nv_bfloat162*)(g_h_lo + o) = pl;
        }
    }
}

// ---- GEMM2: C[128 slots, 128 hidden], K = NI, 22 chunks of 64; scatter-add ----
__global__ __launch_bounds__(256, 1) void k_gemm2(float* __restrict__ out) {
    extern __shared__ char smem[];
    const int e     = blockIdx.z;
    const int start = g_offsets[e];
    const int M     = g_offsets[e + 1] - start;
    const int m0    = blockIdx.y * 128;
    if (m0 >= M) return;
    const int n0 = blockIdx.x * 128;    // gridDim.x = NH/128 = 16

    const int tid  = threadIdx.x;
    const int wid  = tid >> 5;
    const int lane = tid & 31;
    uint32_t sb = smem_u32(smem);

    const int vrow = tid >> 3;
    const int col8 = tid & 7;
    size_t arow[4], brow[4];
#pragma unroll
    for (int i = 0; i < 4; i++) {
        int row = vrow + 32 * i;
        int ar  = m0 + row; if (ar >= M) ar = M - 1;
        arow[i] = (size_t)(start + ar) * NI;
        brow[i] = (size_t)e * NH * NI + (size_t)(n0 + row) * NI;
    }

    auto issue = [&](int s, int kk) {
        uint32_t base = sb + s * STAGE_B;
#pragma unroll
        for (int i = 0; i < 4; i++) {
            int row = vrow + 32 * i;
            uint32_t d = base + row * ROW_B + col8 * 16;
            CP_ASYNC16(d + 0 * TILE_BB, g_h_hi  + arow[i] + kk + col8 * 8);
            CP_ASYNC16(d + 1 * TILE_BB, g_h_lo  + arow[i] + kk + col8 * 8);
            CP_ASYNC16(d + 2 * TILE_BB, g_wdn_hi + brow[i] + kk + col8 * 8);
            CP_ASYNC16(d + 3 * TILE_BB, g_wdn_lo + brow[i] + kk + col8 * 8);
        }
    };

    float acc[16][4];
#pragma unroll
    for (int q = 0; q < 16; q++)
#pragma unroll
        for (int i = 0; i < 4; i++) acc[q][i] = 0.f;

    const uint32_t a_off = (uint32_t)((wid * 16 + (lane & 15)) * ROW_B + (lane >> 4) * 16);
    const uint32_t b_off = (uint32_t)(((lane & 7) + ((lane >> 4) & 1) * 8) * ROW_B +
                                      ((lane >> 3) & 1) * 16);

    issue(0, 0);
    CP_COMMIT();

    for (int c = 0; c < NI / 64; c++) {
        if (c + 1 < NI / 64) { issue((c + 1) & 1, (c + 1) * 64); CP_COMMIT(); CP_WAIT(1); }
        else                 { CP_WAIT(0); }
        __syncthreads();
        uint32_t base = sb + (c & 1) * STAGE_B;
#pragma unroll
        for (int kk = 0; kk < 4; kk++) {
            uint32_t ah[4], al[4];
            LDSM4(ah, base + 0 * TILE_BB + a_off + kk * 32);
            LDSM4(al, base + 1 * TILE_BB + a_off + kk * 32);
#pragma unroll
            for (int nt = 0; nt < 8; nt++) {
                uint32_t bh[4], bl[4];
                uint32_t bo = b_off + nt * (16 * ROW_B) + kk * 32;
                LDSM4(bh, base + 2 * TILE_BB + bo);
                LDSM4(bl, base + 3 * TILE_BB + bo);
                MMA16816(acc[2 * nt],     ah, bh[0], bh[1]);
                MMA16816(acc[2 * nt],     ah, bl[0], bl[1]);
                MMA16816(acc[2 * nt],     al, bh[0], bh[1]);
                MMA16816(acc[2 * nt + 1], ah, bh[2], bh[3]);
                MMA16816(acc[2 * nt + 1], ah, bl[2], bl[3]);
                MMA16816(acc[2 * nt + 1], al, bh[2], bh[3]);
            }
        }
        __syncthreads();
    }

    // epilogue: out[tok, n0+col] += w * acc
    const int r0 = m0 + wid * 16 + (lane >> 2);
    const int r1 = r0 + 8;
    const int cb = (lane & 3) * 2;
#pragma unroll
    for (int half = 0; half < 2; half++) {
        int row = half ? r1 : r0;
        if (row >= M) continue;
        int   tok = g_slot_token[start + row];
        float w   = g_slot_w[start + row];
        float* orow = out + (size_t)tok * NH + n0;
#pragma unroll
        for (int q = 0; q < 16; q++) {
            atomicAdd(orow + q * 8 + cb + 0, w * acc[q][2 * half + 0]);
            atomicAdd(orow + q * 8 + cb + 1, w * acc[q][2 * half + 1]);
        }
    }
}

// ---------------- launch -----------------
extern "C" void kernel_launch(void* const* d_in, const int* in_sizes, int n_in,
                              void* d_out, int out_size) {
    const float* hidden = (const float*)d_in[0];   // [T, H]
    const void*  idx    = d_in[1];                 // [T, K] int32 or int64
    const float* wts    = (const float*)d_in[2];   // [T, K]
    const float* wgu    = (const float*)d_in[3];   // [E, 2I, H]
    const float* wdn    = (const float*)d_in[4];   // [E, H, I]
    (void)in_sizes; (void)n_in;

    cudaFuncSetAttribute(k_gemm1, cudaFuncAttributeMaxDynamicSharedMemorySize, SMEM_TOT);
    cudaFuncSetAttribute(k_gemm2, cudaFuncAttributeMaxDynamicSharedMemorySize, SMEM_TOT);

    // routing
    k_detect<<<1, 32>>>((const int*)idx);
    k_reset<<<1, 32>>>();
    k_count<<<(CAP + 255) / 256, 256>>>(idx);
    k_scan<<<1, 32>>>();
    k_scatter<<<(CAP + 255) / 256, 256>>>(idx, wts);

    // fp32 -> bf16 hi/lo splits
    k_cvt_hid<<<2048, 256>>>((const float4*)hidden);
    k_cvt_wgu<<<8192, 256>>>((const float4*)wgu);
    k_cvt_wdn<<<4096, 256>>>((const float4*)wdn);

    cudaMemsetAsync(d_out, 0, (size_t)out_size * sizeof(float), 0);

    // GEMM1: x = NI/64 = 22 tiles, y = worst-case M tiles, z = experts
    dim3 g1(NI / 64, CAP / 128, NE);
    k_gemm1<<<g1, 256, SMEM_TOT>>>();

    // GEMM2: x = NH/128 = 16 tiles
    dim3 g2(NH / 128, CAP / 128, NE);
    k_gemm2<<<g2, 256, SMEM_TOT>>>((float*)d_out);
}